// round 2
// baseline (speedup 1.0000x reference)
#include <cuda_runtime.h>
#include <math.h>

#define T_DIM 2048
#define C_DIM 512
#define NB 4
#define BATCH 2
#define HALF_C 256
#define SCALE 0.044194173824159216f  // 1/sqrt(512)

// -------- device scratch (no allocs allowed) --------
__device__ float g_q[BATCH * NB * T_DIM * C_DIM];  // [b][n][t][c], rope applied
__device__ float g_v[BATCH * NB * T_DIM * C_DIM];  // [b][n][t][c]
__device__ float g_k[BATCH * T_DIM * C_DIM];       // [b][t][c], rope applied
__device__ float g_y[BATCH * T_DIM * C_DIM];       // [b][t][c]

// ---------------- SGEMM ----------------
#define BM 128
#define BN 128
#define BK 16

// mode 0: Cout[gr*N + gc]   (plain row-major)
// mode 1: branch scatter: n=gc/512, c=gc%512, b=gr/2048, t=gr%2048
//         Cout[((b*NB+n)*T + t)*C + c]
// rope: apply rotary embedding per (t, c) pair in epilogue
__global__ __launch_bounds__(256)
void sgemm_kernel(const float* __restrict__ A, const float* __restrict__ B,
                  float* __restrict__ Cout, int M, int N, int K,
                  int mode, int rope,
                  const float* __restrict__ cosT, const float* __restrict__ sinT)
{
    __shared__ float As[BK][BM];
    __shared__ float Bs[BK][BN];
    const int tid = threadIdx.x;
    const int tx = tid & 15, ty = tid >> 4;
    const int bm = blockIdx.y * BM, bn = blockIdx.x * BN;
    const int aRow = tid >> 2, aCol = (tid & 3) << 2;   // A: 64 rows x 16 cols per half
    const int bRow = tid >> 5, bCol = (tid & 31) << 2;  // B: 8 rows x 128 cols per half

    float acc[8][8];
#pragma unroll
    for (int i = 0; i < 8; i++)
#pragma unroll
        for (int j = 0; j < 8; j++) acc[i][j] = 0.f;

    for (int k0 = 0; k0 < K; k0 += BK) {
#pragma unroll
        for (int r = 0; r < 2; r++) {
            float4 va = *(const float4*)(A + (size_t)(bm + aRow + r * 64) * K + k0 + aCol);
            As[aCol + 0][aRow + r * 64] = va.x;
            As[aCol + 1][aRow + r * 64] = va.y;
            As[aCol + 2][aRow + r * 64] = va.z;
            As[aCol + 3][aRow + r * 64] = va.w;
        }
#pragma unroll
        for (int r = 0; r < 2; r++) {
            *(float4*)(&Bs[bRow + r * 8][bCol]) =
                *(const float4*)(B + (size_t)(k0 + bRow + r * 8) * N + bn + bCol);
        }
        __syncthreads();
#pragma unroll
        for (int kk = 0; kk < BK; kk++) {
            float ar[8], br[8];
#pragma unroll
            for (int i = 0; i < 4; i++) {
                ar[i] = As[kk][ty * 4 + i];
                ar[4 + i] = As[kk][64 + ty * 4 + i];
            }
#pragma unroll
            for (int j = 0; j < 4; j++) {
                br[j] = Bs[kk][tx * 4 + j];
                br[4 + j] = Bs[kk][64 + tx * 4 + j];
            }
#pragma unroll
            for (int i = 0; i < 8; i++)
#pragma unroll
                for (int j = 0; j < 8; j++) acc[i][j] += ar[i] * br[j];
        }
        __syncthreads();
    }

    // epilogue
#pragma unroll
    for (int ig = 0; ig < 2; ig++) {
#pragma unroll
        for (int i = 0; i < 4; i++) {
            const int gr = bm + ig * 64 + ty * 4 + i;
            const int i8 = ig * 4 + i;
            const int trow = gr & (T_DIM - 1);
#pragma unroll
            for (int jg = 0; jg < 2; jg++) {
                const int cbase = bn + jg * 64 + tx * 4;
                float o0 = acc[i8][jg * 4 + 0], o1 = acc[i8][jg * 4 + 1];
                float o2 = acc[i8][jg * 4 + 2], o3 = acc[i8][jg * 4 + 3];
                if (rope) {
                    const int cmod = cbase & (C_DIM - 1);
                    const int f0 = cmod >> 1;  // cbase multiple of 4 -> pairs inside group
                    const float c0 = cosT[trow * HALF_C + f0];
                    const float s0 = sinT[trow * HALF_C + f0];
                    const float c1 = cosT[trow * HALF_C + f0 + 1];
                    const float s1 = sinT[trow * HALF_C + f0 + 1];
                    const float e0 = o0, od0 = o1, e1 = o2, od1 = o3;
                    o0 = e0 * c0 - od0 * s0;
                    o1 = e0 * s0 + od0 * c0;
                    o2 = e1 * c1 - od1 * s1;
                    o3 = e1 * s1 + od1 * c1;
                }
                if (mode == 0) {
                    float* p = Cout + (size_t)gr * N + cbase;
                    p[0] = o0; p[1] = o1; p[2] = o2; p[3] = o3;
                } else {
                    const int n = cbase >> 9;          // branch
                    const int c = cbase & (C_DIM - 1);
                    const int bb = gr >> 11;           // batch
                    float* p = Cout + ((size_t)((bb * NB + n) * T_DIM + trow)) * C_DIM + c;
                    p[0] = o0; p[1] = o1; p[2] = o2; p[3] = o3;
                }
            }
        }
    }
}

// ---------------- attention ----------------
__device__ __forceinline__ float dot4(float4 a, float4 b) {
    return a.x * b.x + a.y * b.y + a.z * b.z + a.w * b.w;
}

// One warp processes query rows t=pr and t=T-1-pr (balanced: 2049 s-iters/warp).
// Online softmax over s of max_n(q_n.k_s)/sqrt(C); V row taken from argmax branch
// (ties summed, matching hard_mask semantics). xor-butterfly sums are bitwise
// identical across lanes, so argmax/tie decisions are warp-coherent.
__global__ __launch_bounds__(128)
void attn_kernel(const float* __restrict__ q, const float* __restrict__ k,
                 const float* __restrict__ v, float* __restrict__ y)
{
    const int warp = threadIdx.x >> 5;
    const int lane = threadIdx.x & 31;
    const int task = blockIdx.x * 4 + warp;  // 0..2047
    const int b = task >> 10;
    const int pr = task & 1023;
    const int coff = lane * 4;  // 4 consecutive floats per lane within each 128-chunk

    const float* kb = k + (size_t)b * T_DIM * C_DIM;
    const float* vbase = v + (size_t)b * NB * T_DIM * C_DIM;

#pragma unroll 1
    for (int half = 0; half < 2; half++) {
        const int t = half ? (T_DIM - 1 - pr) : pr;

        float4 qr[4][4];
#pragma unroll
        for (int n = 0; n < 4; n++)
#pragma unroll
            for (int j = 0; j < 4; j++)
                qr[n][j] = *(const float4*)(q + (size_t)((b * NB + n) * T_DIM + t) * C_DIM +
                                            j * 128 + coff);

        float4 yr[4];
        yr[0] = yr[1] = yr[2] = yr[3] = make_float4(0.f, 0.f, 0.f, 0.f);
        float m = -INFINITY, l = 0.f;

#pragma unroll 2
        for (int s = 0; s <= t; s++) {
            float4 kr[4];
#pragma unroll
            for (int j = 0; j < 4; j++)
                kr[j] = *(const float4*)(kb + (size_t)s * C_DIM + j * 128 + coff);

            float d0 = 0.f, d1 = 0.f, d2 = 0.f, d3 = 0.f;
#pragma unroll
            for (int j = 0; j < 4; j++) {
                d0 += dot4(qr[0][j], kr[j]);
                d1 += dot4(qr[1][j], kr[j]);
                d2 += dot4(qr[2][j], kr[j]);
                d3 += dot4(qr[3][j], kr[j]);
            }
#pragma unroll
            for (int off = 16; off >= 1; off >>= 1) {
                d0 += __shfl_xor_sync(0xffffffffu, d0, off);
                d1 += __shfl_xor_sync(0xffffffffu, d1, off);
                d2 += __shfl_xor_sync(0xffffffffu, d2, off);
                d3 += __shfl_xor_sync(0xffffffffu, d3, off);
            }
            d0 *= SCALE; d1 *= SCALE; d2 *= SCALE; d3 *= SCALE;

            const float amax = fmaxf(fmaxf(d0, d1), fmaxf(d2, d3));
            const float newm = fmaxf(m, amax);
            const float corr = __expf(m - newm);   // exp(-inf)=0 on first iter
            const float p = __expf(amax - newm);
            l = l * corr + p;
#pragma unroll
            for (int j = 0; j < 4; j++) {
                yr[j].x *= corr; yr[j].y *= corr; yr[j].z *= corr; yr[j].w *= corr;
            }
            const float* vrow = vbase + (size_t)s * C_DIM;
#pragma unroll
            for (int n = 0; n < 4; n++) {
                const float dn = (n == 0) ? d0 : (n == 1) ? d1 : (n == 2) ? d2 : d3;
                if (dn == amax) {
                    const float* vp = vrow + (size_t)n * T_DIM * C_DIM;
#pragma unroll
                    for (int j = 0; j < 4; j++) {
                        float4 vv = *(const float4*)(vp + j * 128 + coff);
                        yr[j].x += p * vv.x; yr[j].y += p * vv.y;
                        yr[j].z += p * vv.z; yr[j].w += p * vv.w;
                    }
                }
            }
            m = newm;
        }

        const float inv = 1.f / l;
        float* yo = y + (size_t)(b * T_DIM + t) * C_DIM;
#pragma unroll
        for (int j = 0; j < 4; j++) {
            float4 o = make_float4(yr[j].x * inv, yr[j].y * inv, yr[j].z * inv, yr[j].w * inv);
            *(float4*)(yo + j * 128 + coff) = o;
        }
    }
}

// ---------------- launch ----------------
extern "C" void kernel_launch(void* const* d_in, const int* in_sizes, int n_in,
                              void* d_out, int out_size)
{
    const float* a    = (const float*)d_in[0];
    const float* x    = (const float*)d_in[1];
    const float* Wq   = (const float*)d_in[2];
    const float* Wk   = (const float*)d_in[3];
    const float* Wv   = (const float*)d_in[4];
    const float* Wo   = (const float*)d_in[5];
    const float* cosT = (const float*)d_in[6];
    const float* sinT = (const float*)d_in[7];
    float* out = (float*)d_out;

    float *qp, *vp, *kp, *yp;
    cudaGetSymbolAddress((void**)&qp, g_q);
    cudaGetSymbolAddress((void**)&vp, g_v);
    cudaGetSymbolAddress((void**)&kp, g_k);
    cudaGetSymbolAddress((void**)&yp, g_y);

    const int M = BATCH * T_DIM;  // 4096
    dim3 blk(256);

    // Q = rope(a @ Wq), scattered to [b][n][t][c]
    sgemm_kernel<<<dim3((NB * C_DIM) / BN, M / BM), blk>>>(
        a, Wq, qp, M, NB * C_DIM, C_DIM, 1, 1, cosT, sinT);
    // V = a @ Wv, scattered to [b][n][t][c]
    sgemm_kernel<<<dim3((NB * C_DIM) / BN, M / BM), blk>>>(
        a, Wv, vp, M, NB * C_DIM, C_DIM, 1, 0, cosT, sinT);
    // K = rope(x @ Wk), [b][t][c]
    sgemm_kernel<<<dim3(C_DIM / BN, M / BM), blk>>>(
        x, Wk, kp, M, C_DIM, C_DIM, 0, 1, cosT, sinT);
    // routed causal attention -> y
    attn_kernel<<<(BATCH * T_DIM / 2) / 4, 128>>>(qp, kp, vp, yp);
    // out = y @ Wo
    sgemm_kernel<<<dim3(C_DIM / BN, M / BM), blk>>>(
        yp, Wo, out, M, C_DIM, C_DIM, 0, 0, cosT, sinT);
}

// round 4
// speedup vs baseline: 1.2617x; 1.2617x over previous
#include <cuda_runtime.h>
#include <math.h>

#define T_DIM 2048
#define C_DIM 512
#define NB 4
#define BATCH 2
#define HALF_C 256
#define SCALE 0.044194173824159216f
#define NEGINF -1e30f

#define QT 32
#define ST 64
#define UPB 288
#define UNITS (BATCH * UPB)  // 576

__device__ float g_q[BATCH * NB * T_DIM * C_DIM];
__device__ float g_v[BATCH * NB * T_DIM * C_DIM];
__device__ float g_k[BATCH * T_DIM * C_DIM];
__device__ float g_y[BATCH * T_DIM * C_DIM];
__device__ float g_ypart[(size_t)UNITS * QT * C_DIM];
__device__ float g_mpart[UNITS * QT];
__device__ float g_lpart[UNITS * QT];

// ---------------- SGEMM ----------------
#define BM 128
#define BN 128
#define BK 16

__global__ __launch_bounds__(256)
void sgemm_kernel(const float* __restrict__ A, const float* __restrict__ B,
                  float* __restrict__ Cout, int M, int N, int K,
                  int mode, int rope,
                  const float* __restrict__ cosT, const float* __restrict__ sinT)
{
    __shared__ float As[BK][BM];
    __shared__ float Bs[BK][BN];
    const int tid = threadIdx.x;
    const int tx = tid & 15, ty = tid >> 4;
    const int bm = blockIdx.y * BM, bn = blockIdx.x * BN;
    const int aRow = tid >> 2, aCol = (tid & 3) << 2;
    const int bRow = tid >> 5, bCol = (tid & 31) << 2;

    float acc[8][8];
#pragma unroll
    for (int i = 0; i < 8; i++)
#pragma unroll
        for (int j = 0; j < 8; j++) acc[i][j] = 0.f;

    for (int k0 = 0; k0 < K; k0 += BK) {
#pragma unroll
        for (int r = 0; r < 2; r++) {
            float4 va = *(const float4*)(A + (size_t)(bm + aRow + r * 64) * K + k0 + aCol);
            As[aCol + 0][aRow + r * 64] = va.x;
            As[aCol + 1][aRow + r * 64] = va.y;
            As[aCol + 2][aRow + r * 64] = va.z;
            As[aCol + 3][aRow + r * 64] = va.w;
        }
#pragma unroll
        for (int r = 0; r < 2; r++) {
            *(float4*)(&Bs[bRow + r * 8][bCol]) =
                *(const float4*)(B + (size_t)(k0 + bRow + r * 8) * N + bn + bCol);
        }
        __syncthreads();
#pragma unroll
        for (int kk = 0; kk < BK; kk++) {
            float ar[8], br[8];
#pragma unroll
            for (int i = 0; i < 4; i++) {
                ar[i] = As[kk][ty * 4 + i];
                ar[4 + i] = As[kk][64 + ty * 4 + i];
            }
#pragma unroll
            for (int j = 0; j < 4; j++) {
                br[j] = Bs[kk][tx * 4 + j];
                br[4 + j] = Bs[kk][64 + tx * 4 + j];
            }
#pragma unroll
            for (int i = 0; i < 8; i++)
#pragma unroll
                for (int j = 0; j < 8; j++) acc[i][j] += ar[i] * br[j];
        }
        __syncthreads();
    }

#pragma unroll
    for (int ig = 0; ig < 2; ig++) {
#pragma unroll
        for (int i = 0; i < 4; i++) {
            const int gr = bm + ig * 64 + ty * 4 + i;
            const int i8 = ig * 4 + i;
            const int trow = gr & (T_DIM - 1);
#pragma unroll
            for (int jg = 0; jg < 2; jg++) {
                const int cbase = bn + jg * 64 + tx * 4;
                float o0 = acc[i8][jg * 4 + 0], o1 = acc[i8][jg * 4 + 1];
                float o2 = acc[i8][jg * 4 + 2], o3 = acc[i8][jg * 4 + 3];
                if (rope) {
                    const int cmod = cbase & (C_DIM - 1);
                    const int f0 = cmod >> 1;
                    const float c0 = cosT[trow * HALF_C + f0];
                    const float s0 = sinT[trow * HALF_C + f0];
                    const float c1 = cosT[trow * HALF_C + f0 + 1];
                    const float s1 = sinT[trow * HALF_C + f0 + 1];
                    const float e0 = o0, od0 = o1, e1 = o2, od1 = o3;
                    o0 = e0 * c0 - od0 * s0;
                    o1 = e0 * s0 + od0 * c0;
                    o2 = e1 * c1 - od1 * s1;
                    o3 = e1 * s1 + od1 * c1;
                }
                if (mode == 0) {
                    float* p = Cout + (size_t)gr * N + cbase;
                    p[0] = o0; p[1] = o1; p[2] = o2; p[3] = o3;
                } else {
                    const int n = cbase >> 9;
                    const int c = cbase & (C_DIM - 1);
                    const int bb = gr >> 11;
                    float* p = Cout + ((size_t)((bb * NB + n) * T_DIM + trow)) * C_DIM + c;
                    p[0] = o0; p[1] = o1; p[2] = o2; p[3] = o3;
                }
            }
        }
    }
}

// ---------------- tiled routed flash attention ----------------
__global__ __launch_bounds__(256)
void attn_tile_kernel(const float* __restrict__ q, const float* __restrict__ k,
                      const float* __restrict__ v)
{
    __shared__ float Qs[16][129];
    __shared__ float Ks[16][68];
    __shared__ float Pp[ST][QT + 1];
    __shared__ int   Bm[ST][QT + 1];
    __shared__ float Corr[QT];

    const int tid = threadIdx.x;
    const int b = blockIdx.x / UPB;
    int u = blockIdx.x % UPB;
    int qt = 0;
    {
        int acc = 0;
        for (int j = 0; j < 64; j++) {
            int c = (j >> 3) + 1;
            if (u < acc + c) { qt = j; u -= acc; break; }
            acc += c;
        }
    }
    const int s_begin = u * 256;
    const int s_end = min(s_begin + 256, qt * 32 + 32);

    const int tq = tid >> 3, ts = tid & 7;
    const int ts8 = ts * 8;
    const int t_glob = qt * 32 + tq;
    const int warp = tid >> 5, lane = tid & 31;

    const float* kb = k + (size_t)b * T_DIM * C_DIM;
    const float* qb = q + (size_t)b * NB * T_DIM * C_DIM;
    const float* vb = v + (size_t)b * NB * T_DIM * C_DIM;

    float m = NEGINF, l = 0.f;
    float4 y[4][4];
#pragma unroll
    for (int a = 0; a < 4; a++)
#pragma unroll
        for (int i = 0; i < 4; i++) y[a][i] = make_float4(0.f, 0.f, 0.f, 0.f);

    const int qrow = tid >> 1;
    const int qhalf = (tid & 1) * 8;
    const float* qsrc = qb + ((size_t)(qrow >> 5) * T_DIM + qt * 32 + (qrow & 31)) * C_DIM;
    const int krow = tid >> 2;
    const int kcol = (tid & 3) * 4;

    for (int s0 = s_begin; s0 < s_end; s0 += ST) {
        float d[4][8];
#pragma unroll
        for (int n = 0; n < 4; n++)
#pragma unroll
            for (int j = 0; j < 8; j++) d[n][j] = 0.f;

        for (int k0 = 0; k0 < C_DIM; k0 += 16) {
            float4 v0 = *(const float4*)(qsrc + k0 + qhalf);
            float4 v1 = *(const float4*)(qsrc + k0 + qhalf + 4);
            Qs[qhalf + 0][qrow] = v0.x; Qs[qhalf + 1][qrow] = v0.y;
            Qs[qhalf + 2][qrow] = v0.z; Qs[qhalf + 3][qrow] = v0.w;
            Qs[qhalf + 4][qrow] = v1.x; Qs[qhalf + 5][qrow] = v1.y;
            Qs[qhalf + 6][qrow] = v1.z; Qs[qhalf + 7][qrow] = v1.w;
            float4 kv = *(const float4*)(kb + (size_t)(s0 + krow) * C_DIM + k0 + kcol);
            Ks[kcol + 0][krow] = kv.x; Ks[kcol + 1][krow] = kv.y;
            Ks[kcol + 2][krow] = kv.z; Ks[kcol + 3][krow] = kv.w;
            __syncthreads();
#pragma unroll
            for (int kk = 0; kk < 16; kk++) {
                const float a0 = Qs[kk][tq], a1 = Qs[kk][32 + tq];
                const float a2 = Qs[kk][64 + tq], a3 = Qs[kk][96 + tq];
                const float4 b0 = *(const float4*)&Ks[kk][ts8];
                const float4 b1 = *(const float4*)&Ks[kk][ts8 + 4];
#define FM(n, an) \
    d[n][0] += an * b0.x; d[n][1] += an * b0.y; d[n][2] += an * b0.z; d[n][3] += an * b0.w; \
    d[n][4] += an * b1.x; d[n][5] += an * b1.y; d[n][6] += an * b1.z; d[n][7] += an * b1.w;
                FM(0, a0) FM(1, a1) FM(2, a2) FM(3, a3)
#undef FM
            }
            __syncthreads();
        }

        // routing + tile softmax
        float amax[8];
        int msk[8];
        float tmax = NEGINF;
#pragma unroll
        for (int j = 0; j < 8; j++) {
            const int sg = s0 + ts8 + j;
            const float d0 = d[0][j] * SCALE, d1 = d[1][j] * SCALE;
            const float d2 = d[2][j] * SCALE, d3 = d[3][j] * SCALE;
            float am = fmaxf(fmaxf(d0, d1), fmaxf(d2, d3));
            int mk = (d0 == am ? 1 : 0) | (d1 == am ? 2 : 0) |
                     (d2 == am ? 4 : 0) | (d3 == am ? 8 : 0);
            if (sg > t_glob) am = NEGINF;
            amax[j] = am; msk[j] = mk;
            tmax = fmaxf(tmax, am);
        }
        tmax = fmaxf(tmax, __shfl_xor_sync(0xffffffffu, tmax, 1));
        tmax = fmaxf(tmax, __shfl_xor_sync(0xffffffffu, tmax, 2));
        tmax = fmaxf(tmax, __shfl_xor_sync(0xffffffffu, tmax, 4));
        const float nm = fmaxf(m, tmax);
        const float corr = __expf(m - nm);
        float psum = 0.f;
#pragma unroll
        for (int j = 0; j < 8; j++) {
            const float p = (amax[j] <= NEGINF) ? 0.f : __expf(amax[j] - nm);
            Pp[ts8 + j][tq] = p;
            Bm[ts8 + j][tq] = msk[j];
            psum += p;
        }
        psum += __shfl_xor_sync(0xffffffffu, psum, 1);
        psum += __shfl_xor_sync(0xffffffffu, psum, 2);
        psum += __shfl_xor_sync(0xffffffffu, psum, 4);
        l = l * corr + psum;
        m = nm;
        if (ts == 0) Corr[tq] = corr;
        __syncthreads();

        // PV: warp owns q rows {warp, warp+8, warp+16, warp+24}, lane owns c = i*128 + lane*4
#pragma unroll
        for (int a = 0; a < 4; a++) {
            const float c = Corr[warp + a * 8];
#pragma unroll
            for (int i = 0; i < 4; i++) {
                y[a][i].x *= c; y[a][i].y *= c; y[a][i].z *= c; y[a][i].w *= c;
            }
        }
        for (int s = 0; s < ST; s++) {
            const float* vrow = vb + (size_t)(s0 + s) * C_DIM;
#pragma unroll
            for (int a = 0; a < 4; a++) {
                const float p = Pp[s][warp + a * 8];
                if (p != 0.f) {
                    const int mk = Bm[s][warp + a * 8];
#pragma unroll
                    for (int n = 0; n < 4; n++) {
                        if (mk & (1 << n)) {
                            const float* vp = vrow + (size_t)n * T_DIM * C_DIM;
#pragma unroll
                            for (int i = 0; i < 4; i++) {
                                const float4 vv = *(const float4*)(vp + i * 128 + lane * 4);
                                y[a][i].x += p * vv.x; y[a][i].y += p * vv.y;
                                y[a][i].z += p * vv.z; y[a][i].w += p * vv.w;
                            }
                        }
                    }
                }
            }
        }
        __syncthreads();
    }

    const int unit = blockIdx.x;
#pragma unroll
    for (int a = 0; a < 4; a++) {
        float* yp = g_ypart + ((size_t)unit * QT + (warp + a * 8)) * C_DIM;
#pragma unroll
        for (int i = 0; i < 4; i++)
            *(float4*)(yp + i * 128 + lane * 4) = y[a][i];
    }
    if (ts == 0) {
        g_mpart[unit * QT + tq] = m;
        g_lpart[unit * QT + tq] = l;
    }
}

// ---------------- combine partials ----------------
__global__ __launch_bounds__(256)
void combine_kernel(float* __restrict__ yout)
{
    const int blk = blockIdx.x;         // b*64 + qt
    const int b = blk >> 6, qt = blk & 63;
    const int tid = threadIdx.x;
    const int qq = tid >> 3, cg = tid & 7;
    const int g = qt >> 3, r = qt & 7;
    const int base = qt + 4 * g * (g - 1) + r * g;  // prefix sum S(qt)
    const int nch = g + 1;
    const int ubase = b * UPB + base;

    float mstar = NEGINF;
    for (int c = 0; c < nch; c++)
        mstar = fmaxf(mstar, g_mpart[(ubase + c) * QT + qq]);

    float4 acc[16];
#pragma unroll
    for (int i = 0; i < 16; i++) acc[i] = make_float4(0.f, 0.f, 0.f, 0.f);
    float ltot = 0.f;
    for (int c = 0; c < nch; c++) {
        const float mi = g_mpart[(ubase + c) * QT + qq];
        const float li = g_lpart[(ubase + c) * QT + qq];
        const float f = __expf(mi - mstar);
        ltot += f * li;
        const float* yp = g_ypart + ((size_t)(ubase + c) * QT + qq) * C_DIM + cg * 64;
#pragma unroll
        for (int i = 0; i < 16; i++) {
            const float4 vv = *(const float4*)(yp + i * 4);
            acc[i].x += f * vv.x; acc[i].y += f * vv.y;
            acc[i].z += f * vv.z; acc[i].w += f * vv.w;
        }
    }
    const float inv = 1.f / ltot;
    float* out = yout + ((size_t)(b * T_DIM + qt * 32 + qq)) * C_DIM + cg * 64;
#pragma unroll
    for (int i = 0; i < 16; i++) {
        float4 o = make_float4(acc[i].x * inv, acc[i].y * inv, acc[i].z * inv, acc[i].w * inv);
        *(float4*)(out + i * 4) = o;
    }
}

// ---------------- launch ----------------
extern "C" void kernel_launch(void* const* d_in, const int* in_sizes, int n_in,
                              void* d_out, int out_size)
{
    const float* a    = (const float*)d_in[0];
    const float* x    = (const float*)d_in[1];
    const float* Wq   = (const float*)d_in[2];
    const float* Wk   = (const float*)d_in[3];
    const float* Wv   = (const float*)d_in[4];
    const float* Wo   = (const float*)d_in[5];
    const float* cosT = (const float*)d_in[6];
    const float* sinT = (const float*)d_in[7];
    float* out = (float*)d_out;

    float *qp, *vp, *kp, *yp;
    cudaGetSymbolAddress((void**)&qp, g_q);
    cudaGetSymbolAddress((void**)&vp, g_v);
    cudaGetSymbolAddress((void**)&kp, g_k);
    cudaGetSymbolAddress((void**)&yp, g_y);

    const int M = BATCH * T_DIM;
    dim3 blk(256);

    sgemm_kernel<<<dim3((NB * C_DIM) / BN, M / BM), blk>>>(
        a, Wq, qp, M, NB * C_DIM, C_DIM, 1, 1, cosT, sinT);
    sgemm_kernel<<<dim3((NB * C_DIM) / BN, M / BM), blk>>>(
        a, Wv, vp, M, NB * C_DIM, C_DIM, 1, 0, cosT, sinT);
    sgemm_kernel<<<dim3(C_DIM / BN, M / BM), blk>>>(
        x, Wk, kp, M, C_DIM, C_DIM, 0, 1, cosT, sinT);
    attn_tile_kernel<<<UNITS, 256>>>(qp, kp, vp);
    combine_kernel<<<BATCH * 64, 256>>>(yp);
    sgemm_kernel<<<dim3(C_DIM / BN, M / BM), blk>>>(
        yp, Wo, out, M, C_DIM, C_DIM, 0, 0, cosT, sinT);
}